// round 4
// baseline (speedup 1.0000x reference)
#include <cuda_runtime.h>
#include <math.h>

#define BB 64
#define NN 512
#define EE 128
#define FEATN 33
#define ROWS (BB*NN)
#define LARGEF 1000000.0f

__device__ float g_feat[(size_t)ROWS * FEATN];
__device__ int   g_maskmode;

// ---------------------------------------------------------------------------
// packed f32x2 helpers (Blackwell fma.rn.f32x2 — not emitted by ptxas from C++)
// ---------------------------------------------------------------------------
__device__ __forceinline__ unsigned long long pack2(float a, float b) {
    unsigned long long r;
    asm("mov.b64 %0, {%1, %2};" : "=l"(r) : "f"(a), "f"(b));
    return r;
}
__device__ __forceinline__ void unpack2(unsigned long long v, float &a, float &b) {
    asm("mov.b64 {%0, %1}, %2;" : "=f"(a), "=f"(b) : "l"(v));
}
__device__ __forceinline__ void ffma2(unsigned long long &d, unsigned long long a,
                                      unsigned long long b) {
    asm("fma.rn.f32x2 %0, %1, %2, %0;" : "+l"(d) : "l"(a), "l"(b));
}

// ---------------------------------------------------------------------------
// Mask dtype detection v2: 1024 threads, uint4 loads (8192 words = 2048 uint4)
// ---------------------------------------------------------------------------
__global__ __launch_bounds__(1024) void detect_mask_kernel(const uint4* __restrict__ mw) {
    __shared__ int sU, sF;
    if (threadIdx.x == 0) { sU = 0; sF = 0; }
    __syncthreads();
    int u = 0, f = 0;
#pragma unroll
    for (int r = 0; r < 2; r++) {
        uint4 v = mw[threadIdx.x + r * 1024];
        unsigned w;
        w = v.x; if (w == 0x3F800000u) f = 1; else if (w > 1u) u = 1;
        w = v.y; if (w == 0x3F800000u) f = 1; else if (w > 1u) u = 1;
        w = v.z; if (w == 0x3F800000u) f = 1; else if (w > 1u) u = 1;
        w = v.w; if (w == 0x3F800000u) f = 1; else if (w > 1u) u = 1;
    }
    if (u) atomicOr(&sU, 1);
    if (f) atomicOr(&sF, 1);
    __syncthreads();
    if (threadIdx.x == 0) g_maskmode = sU ? 1 : (sF ? 2 : 0);
}

// ---------------------------------------------------------------------------
// Feature kernel: one warp per (b, i) row; lanes stride over j. Squared domain.
// ---------------------------------------------------------------------------
__device__ __forceinline__ float wsum(float v) {
#pragma unroll
    for (int o = 16; o > 0; o >>= 1) v += __shfl_xor_sync(0xFFFFFFFFu, v, o);
    return v;
}
__device__ __forceinline__ float wmin(float v) {
#pragma unroll
    for (int o = 16; o > 0; o >>= 1) v = fminf(v, __shfl_xor_sync(0xFFFFFFFFu, v, o));
    return v;
}

__global__ __launch_bounds__(256) void feat_kernel(const float* __restrict__ pos,
                                                   const void* __restrict__ mask) {
    __shared__ float4 sp[NN];
    const int b   = blockIdx.y;
    const int tid = threadIdx.x;
    const int mode = g_maskmode;

    for (int idx = tid; idx < NN; idx += 256) {
        const int gi = b * NN + idx;
        float px = pos[gi * 2 + 0];
        float py = pos[gi * 2 + 1];
        bool m;
        if (mode == 1)      m = ((const unsigned char*)mask)[gi] != 0;
        else if (mode == 2) m = ((const float*)mask)[gi] != 0.0f;
        else                m = ((const int*)mask)[gi] != 0;
        sp[idx] = make_float4(px, py, m ? 0.0f : 1.0f, 0.0f);
    }
    __syncthreads();

    const int warp = tid >> 5, lane = tid & 31;
    const int i = blockIdx.x * 8 + warp;
    const float4 pi = sp[i];
    const float xi = pi.x, yi = pi.y;

    unsigned long long cntDT = 0ull;   // 12 counters: dir(0/20/40) x thresh(5-bit fields)
    unsigned scntLo = 0u, scntHi = 0u; // 8 sector counters, 8-bit fields
    float mdUp2 = LARGEF, mdDn2 = LARGEF, mdLat2 = LARGEF;
    float smin2[8];
#pragma unroll
    for (int k = 0; k < 8; k++) smin2[k] = LARGEF;
    float sumd = 0.0f;

#pragma unroll 4
    for (int j0 = 0; j0 < 16; j0++) {
        const int j = lane + (j0 << 5);
        const float4 p = sp[j];
        const float dx = p.x - xi;
        const float dy = p.y - yi;
        const float d2 = __fadd_rn(__fadd_rn(__fmul_rn(dx, dx), __fmul_rn(dy, dy)), 1e-8f);
        const bool  valid = (p.z != 0.0f) && (j != i);
        const float q2 = valid ? d2 : LARGEF;

        const float hay = 0.5f * fabsf(dy);
        const bool up = dx >  hay;
        const bool dn = dx < -hay;

        unsigned pat = (q2 < 9.0f)   ? 0x8421u
                     : (q2 < 25.0f)  ? 0x8420u
                     : (q2 < 64.0f)  ? 0x8400u
                     : (q2 < 144.0f) ? 0x8000u : 0u;
        const int dsh = up ? 0 : (dn ? 20 : 40);
        cntDT += (unsigned long long)pat << dsh;

        mdUp2  = fminf(mdUp2,  up ? q2 : LARGEF);
        mdDn2  = fminf(mdDn2,  dn ? q2 : LARGEF);
        mdLat2 = fminf(mdLat2, (!up && !dn) ? q2 : LARGEF);

        const float su = dx + dy, sv = dy - dx;
        const int s = (dy < 0.0f)
            ? ((dx < 0.0f) ? ((sv > 0.0f) ? 0 : 1) : ((su < 0.0f) ? 2 : 3))
            : ((dx > 0.0f) ? ((sv < 0.0f) ? 4 : 5) : ((su > 0.0f) ? 6 : 7));

        const unsigned sinc = valid ? (1u << ((s & 3) << 3)) : 0u;
        if (s < 4) scntLo += sinc; else scntHi += sinc;
#pragma unroll
        for (int k = 0; k < 8; k++)
            if (s == k) smin2[k] = fminf(smin2[k], q2);

        const float dist = d2 * rsqrtf(d2);
        sumd += valid ? dist : 0.0f;
    }

    float cnt[12];
#pragma unroll
    for (int d = 0; d < 3; d++)
#pragma unroll
        for (int t = 0; t < 4; t++)
            cnt[d * 4 + t] = (float)((unsigned)(cntDT >> (d * 20 + t * 5)) & 31u);
    float sc[8];
#pragma unroll
    for (int k = 0; k < 8; k++)
        sc[k] = (float)(((k < 4 ? (scntLo >> (k * 8)) : (scntHi >> ((k - 4) * 8)))) & 255u);

#pragma unroll
    for (int q = 0; q < 12; q++) cnt[q] = wsum(cnt[q]);
#pragma unroll
    for (int k = 0; k < 8; k++) { sc[k] = wsum(sc[k]); smin2[k] = wmin(smin2[k]); }
    mdUp2 = wmin(mdUp2); mdDn2 = wmin(mdDn2); mdLat2 = wmin(mdLat2);
    sumd = wsum(sumd);

    if (lane == 0) {
        float* o = g_feat + (size_t)(b * NN + i) * FEATN;
#pragma unroll
        for (int t = 0; t < 4; t++) {
            o[t * 3 + 0] = cnt[0 * 4 + t];
            o[t * 3 + 1] = cnt[1 * 4 + t];
            o[t * 3 + 2] = cnt[2 * 4 + t];
        }
        o[12] = fminf(sqrtf(mdUp2)  / 10.0f, 1.0f);
        o[13] = fminf(sqrtf(mdDn2)  / 10.0f, 1.0f);
        o[14] = fminf(sqrtf(mdLat2) / 10.0f, 1.0f);
        float cntv = 0.0f;
#pragma unroll
        for (int k = 0; k < 8; k++) {
            o[15 + 2 * k] = sc[k];
            o[16 + 2 * k] = fminf(sqrtf(smin2[k]) / 10.0f, 1.0f);
            cntv += sc[k];            // valid count = sum of sector counts
        }
        o[31] = cnt[3] + cnt[7] + cnt[11];
        float vc = fmaxf(cntv, 1.0f);
        o[32] = fminf(sumd / vc / 10.0f, 1.0f);
    }
}

// ---------------------------------------------------------------------------
// Encoder v4: 64 rows/block, 256 threads, packed f32x2 FMA throughout.
// Thread = 2 cols (c0, c0+1) x 16 rows. Accumulators hold {even-k, odd-k}
// partials packed in 64-bit; h/x shared rows reinterpret as ulonglong2.
// ---------------------------------------------------------------------------
#define XP 36
#define HP 132

__global__ __launch_bounds__(256, 2) void encoder_kernel(
    const float* __restrict__ W1, const float* __restrict__ b1,
    const float* __restrict__ gamma, const float* __restrict__ beta,
    const float* __restrict__ W2, const float* __restrict__ b2,
    float* __restrict__ out)
{
    __shared__ float sx[64 * XP];
    __shared__ float sh[64 * HP];
    __shared__ float sred[64 * 4];

    const int tid   = threadIdx.x;
    const int cg    = tid & 63;
    const int rg    = tid >> 6;        // 0..3
    const int lane  = tid & 31;
    const int whalf = cg >> 5;
    const int c0    = cg * 2;
    const int r0    = rg * 16;
    const int rowBase = blockIdx.x * 64;

    for (int idx = tid; idx < 64 * FEATN; idx += 256) {
        int r = idx / FEATN, f = idx - r * FEATN;
        sx[r * XP + f] = g_feat[(size_t)rowBase * FEATN + idx];
    }
    for (int idx = tid; idx < 64 * 3; idx += 256) {
        int r = idx / 3;
        sx[r * XP + FEATN + idx % 3] = 0.0f;
    }
    __syncthreads();

    // ---- GEMM1: h = x @ W1 + b1 (packed f32x2 over k pairs) ----
    float accA[16], accB[16];
    {
        unsigned long long aA[16], aB[16];
        const float2 bb = __ldg((const float2*)&b1[c0]);
#pragma unroll
        for (int rr = 0; rr < 16; rr++) {
            aA[rr] = pack2(bb.x, 0.0f);
            aB[rr] = pack2(bb.y, 0.0f);
        }
#pragma unroll 2
        for (int f4 = 0; f4 < 32; f4 += 4) {
            const float2 w0 = __ldg((const float2*)&W1[(f4 + 0) * EE + c0]);
            const float2 w1 = __ldg((const float2*)&W1[(f4 + 1) * EE + c0]);
            const float2 w2 = __ldg((const float2*)&W1[(f4 + 2) * EE + c0]);
            const float2 w3 = __ldg((const float2*)&W1[(f4 + 3) * EE + c0]);
            const unsigned long long wA01 = pack2(w0.x, w1.x);
            const unsigned long long wA23 = pack2(w2.x, w3.x);
            const unsigned long long wB01 = pack2(w0.y, w1.y);
            const unsigned long long wB23 = pack2(w2.y, w3.y);
#pragma unroll
            for (int rr = 0; rr < 16; rr++) {
                const ulonglong2 xv = *(const ulonglong2*)&sx[(r0 + rr) * XP + f4];
                ffma2(aA[rr], xv.x, wA01);
                ffma2(aA[rr], xv.y, wA23);
                ffma2(aB[rr], xv.x, wB01);
                ffma2(aB[rr], xv.y, wB23);
            }
        }
        const float2 wl = __ldg((const float2*)&W1[32 * EE + c0]);
#pragma unroll
        for (int rr = 0; rr < 16; rr++) {
            float lo, hi;
            const float xl = sx[(r0 + rr) * XP + 32];
            unpack2(aA[rr], lo, hi); accA[rr] = lo + hi + xl * wl.x;
            unpack2(aB[rr], lo, hi); accB[rr] = lo + hi + xl * wl.y;
        }
    }

    // ---- LN partials ----
#pragma unroll
    for (int rr = 0; rr < 16; rr++) {
        float s  = wsum(accA[rr] + accB[rr]);
        float sq = wsum(accA[rr] * accA[rr] + accB[rr] * accB[rr]);
        if (lane == 0) {
            const int r = r0 + rr;
            sred[r * 4 + whalf * 2 + 0] = s;
            sred[r * 4 + whalf * 2 + 1] = sq;
        }
    }
    __syncthreads();

    const float2 gv  = __ldg((const float2*)&gamma[c0]);
    const float2 bev = __ldg((const float2*)&beta[c0]);
#pragma unroll
    for (int rr = 0; rr < 16; rr++) {
        const int r = r0 + rr;
        const float s  = sred[r * 4 + 0] + sred[r * 4 + 2];
        const float sq = sred[r * 4 + 1] + sred[r * 4 + 3];
        const float mu  = s * (1.0f / 128.0f);
        const float var = sq * (1.0f / 128.0f) - mu * mu;
        const float inv = 1.0f / sqrtf(var + 1e-5f);
        float hA = (accA[rr] - mu) * inv * gv.x + bev.x;
        float hB = (accB[rr] - mu) * inv * gv.y + bev.y;
        hA = 0.5f * hA * (1.0f + erff(hA * 0.70710678118654752440f));
        hB = 0.5f * hB * (1.0f + erff(hB * 0.70710678118654752440f));
        *(float2*)&sh[r * HP + c0] = make_float2(hA, hB);
    }
    __syncthreads();

    // ---- GEMM2: out = h @ W2 + b2 (packed f32x2 over k pairs) ----
    {
        unsigned long long aA[16], aB[16];
        const float2 bo = __ldg((const float2*)&b2[c0]);
#pragma unroll
        for (int rr = 0; rr < 16; rr++) {
            aA[rr] = pack2(bo.x, 0.0f);
            aB[rr] = pack2(bo.y, 0.0f);
        }
#pragma unroll 2
        for (int k4 = 0; k4 < EE; k4 += 4) {
            const float2 w0 = __ldg((const float2*)&W2[(k4 + 0) * EE + c0]);
            const float2 w1 = __ldg((const float2*)&W2[(k4 + 1) * EE + c0]);
            const float2 w2 = __ldg((const float2*)&W2[(k4 + 2) * EE + c0]);
            const float2 w3 = __ldg((const float2*)&W2[(k4 + 3) * EE + c0]);
            const unsigned long long wA01 = pack2(w0.x, w1.x);
            const unsigned long long wA23 = pack2(w2.x, w3.x);
            const unsigned long long wB01 = pack2(w0.y, w1.y);
            const unsigned long long wB23 = pack2(w2.y, w3.y);
#pragma unroll
            for (int rr = 0; rr < 16; rr++) {
                const ulonglong2 hv = *(const ulonglong2*)&sh[(r0 + rr) * HP + k4];
                ffma2(aA[rr], hv.x, wA01);
                ffma2(aA[rr], hv.y, wA23);
                ffma2(aB[rr], hv.x, wB01);
                ffma2(aB[rr], hv.y, wB23);
            }
        }
#pragma unroll
        for (int rr = 0; rr < 16; rr++) {
            float loA, hiA, loB, hiB;
            unpack2(aA[rr], loA, hiA);
            unpack2(aB[rr], loB, hiB);
            float2 o2 = make_float2(loA + hiA, loB + hiB);
            *(float2*)&out[(size_t)(rowBase + r0 + rr) * EE + c0] = o2;
        }
    }
}

// ---------------------------------------------------------------------------
extern "C" void kernel_launch(void* const* d_in, const int* in_sizes, int n_in,
                              void* d_out, int out_size) {
    const float* positions = (const float*)d_in[0];
    const void*  mask      = d_in[1];
    const float* W1        = (const float*)d_in[2];
    const float* b1        = (const float*)d_in[3];
    const float* gamma     = (const float*)d_in[4];
    const float* beta      = (const float*)d_in[5];
    const float* W2        = (const float*)d_in[6];
    const float* b2        = (const float*)d_in[7];
    float* out = (float*)d_out;

    detect_mask_kernel<<<1, 1024>>>((const uint4*)mask);
    feat_kernel<<<dim3(NN / 8, BB), 256>>>(positions, mask);
    encoder_kernel<<<ROWS / 64, 256>>>(W1, b1, gamma, beta, W2, b2, out);
}

// round 5
// speedup vs baseline: 1.0758x; 1.0758x over previous
#include <cuda_runtime.h>
#include <math.h>

#define BB 64
#define NN 512
#define EE 128
#define FEATN 33
#define ROWS (BB*NN)
#define LARGEF 1000000.0f

__device__ float g_feat[(size_t)ROWS * FEATN];

// ---------------------------------------------------------------------------
// Feature kernel: one warp per (b, i) row; lanes stride over j. Squared domain.
// Mask dtype (u8 / i32 / f32) detected inline per block from the first 4KB.
// ---------------------------------------------------------------------------
__device__ __forceinline__ float wsum(float v) {
#pragma unroll
    for (int o = 16; o > 0; o >>= 1) v += __shfl_xor_sync(0xFFFFFFFFu, v, o);
    return v;
}
__device__ __forceinline__ float wmin(float v) {
#pragma unroll
    for (int o = 16; o > 0; o >>= 1) v = fminf(v, __shfl_xor_sync(0xFFFFFFFFu, v, o));
    return v;
}

__global__ __launch_bounds__(256) void feat_kernel(const float* __restrict__ pos,
                                                   const void* __restrict__ mask) {
    __shared__ float4 sp[NN];
    const int b   = blockIdx.y;
    const int tid = threadIdx.x;

    // ---- inline mask dtype detection (first 256 uint4 = 4KB) ----
    int flags;
    {
        const uint4 v = ((const uint4*)mask)[tid];
        int u = 0, f = 0;
        unsigned w;
        w = v.x; if (w == 0x3F800000u) f = 1; else if (w > 1u) u = 1;
        w = v.y; if (w == 0x3F800000u) f = 1; else if (w > 1u) u = 1;
        w = v.z; if (w == 0x3F800000u) f = 1; else if (w > 1u) u = 1;
        w = v.w; if (w == 0x3F800000u) f = 1; else if (w > 1u) u = 1;
        flags = __syncthreads_or(u | (f << 1));
    }
    const int mode = (flags & 1) ? 1 : ((flags & 2) ? 2 : 0);

    for (int idx = tid; idx < NN; idx += 256) {
        const int gi = b * NN + idx;
        float px = pos[gi * 2 + 0];
        float py = pos[gi * 2 + 1];
        bool m;
        if (mode == 1)      m = ((const unsigned char*)mask)[gi] != 0;
        else if (mode == 2) m = ((const float*)mask)[gi] != 0.0f;
        else                m = ((const int*)mask)[gi] != 0;
        sp[idx] = make_float4(px, py, m ? 0.0f : 1.0f, 0.0f);
    }
    __syncthreads();

    const int warp = tid >> 5, lane = tid & 31;
    const int i = blockIdx.x * 8 + warp;
    const float4 pi = sp[i];
    const float xi = pi.x, yi = pi.y;

    // duplicated accumulators (even/odd iteration) to break serial RAW chains
    unsigned long long cntDT0 = 0ull, cntDT1 = 0ull;
    unsigned scntLo0 = 0u, scntLo1 = 0u, scntHi0 = 0u, scntHi1 = 0u;
    float sumd0 = 0.0f, sumd1 = 0.0f;
    float mdUp2 = LARGEF, mdDn2 = LARGEF, mdLat2 = LARGEF;
    float smin2[8];
#pragma unroll
    for (int k = 0; k < 8; k++) smin2[k] = LARGEF;

#pragma unroll 4
    for (int j0 = 0; j0 < 16; j0++) {
        const int j = lane + (j0 << 5);
        const float4 p = sp[j];
        const float dx = p.x - xi;
        const float dy = p.y - yi;
        const float d2 = __fadd_rn(__fadd_rn(__fmul_rn(dx, dx), __fmul_rn(dy, dy)), 1e-8f);
        const bool  valid = (p.z != 0.0f) && (j != i);
        const float q2 = valid ? d2 : LARGEF;

        const float hay = 0.5f * fabsf(dy);
        const bool up = dx >  hay;
        const bool dn = dx < -hay;

        unsigned pat = (q2 < 9.0f)   ? 0x8421u
                     : (q2 < 25.0f)  ? 0x8420u
                     : (q2 < 64.0f)  ? 0x8400u
                     : (q2 < 144.0f) ? 0x8000u : 0u;
        const int dsh = up ? 0 : (dn ? 20 : 40);
        const unsigned long long inc = (unsigned long long)pat << dsh;
        if (j0 & 1) cntDT1 += inc; else cntDT0 += inc;

        mdUp2  = fminf(mdUp2,  up ? q2 : LARGEF);
        mdDn2  = fminf(mdDn2,  dn ? q2 : LARGEF);
        mdLat2 = fminf(mdLat2, (!up && !dn) ? q2 : LARGEF);

        const float su = dx + dy, sv = dy - dx;
        const int s = (dy < 0.0f)
            ? ((dx < 0.0f) ? ((sv > 0.0f) ? 0 : 1) : ((su < 0.0f) ? 2 : 3))
            : ((dx > 0.0f) ? ((sv < 0.0f) ? 4 : 5) : ((su > 0.0f) ? 6 : 7));

        const unsigned sinc = valid ? (1u << ((s & 3) << 3)) : 0u;
        if (j0 & 1) { if (s < 4) scntLo1 += sinc; else scntHi1 += sinc; }
        else        { if (s < 4) scntLo0 += sinc; else scntHi0 += sinc; }
#pragma unroll
        for (int k = 0; k < 8; k++)
            if (s == k) smin2[k] = fminf(smin2[k], q2);

        const float dist = d2 * rsqrtf(d2);
        if (j0 & 1) sumd1 += valid ? dist : 0.0f;
        else        sumd0 += valid ? dist : 0.0f;
    }

    const unsigned long long cntDT = cntDT0 + cntDT1;
    const unsigned scntLo = scntLo0 + scntLo1;
    const unsigned scntHi = scntHi0 + scntHi1;
    float sumd = sumd0 + sumd1;

    float cnt[12];
#pragma unroll
    for (int d = 0; d < 3; d++)
#pragma unroll
        for (int t = 0; t < 4; t++)
            cnt[d * 4 + t] = (float)((unsigned)(cntDT >> (d * 20 + t * 5)) & 31u);
    float sc[8];
#pragma unroll
    for (int k = 0; k < 8; k++)
        sc[k] = (float)(((k < 4 ? (scntLo >> (k * 8)) : (scntHi >> ((k - 4) * 8)))) & 255u);

#pragma unroll
    for (int q = 0; q < 12; q++) cnt[q] = wsum(cnt[q]);
#pragma unroll
    for (int k = 0; k < 8; k++) { sc[k] = wsum(sc[k]); smin2[k] = wmin(smin2[k]); }
    mdUp2 = wmin(mdUp2); mdDn2 = wmin(mdDn2); mdLat2 = wmin(mdLat2);
    sumd = wsum(sumd);

    if (lane == 0) {
        float* o = g_feat + (size_t)(b * NN + i) * FEATN;
#pragma unroll
        for (int t = 0; t < 4; t++) {
            o[t * 3 + 0] = cnt[0 * 4 + t];
            o[t * 3 + 1] = cnt[1 * 4 + t];
            o[t * 3 + 2] = cnt[2 * 4 + t];
        }
        o[12] = fminf(sqrtf(mdUp2)  / 10.0f, 1.0f);
        o[13] = fminf(sqrtf(mdDn2)  / 10.0f, 1.0f);
        o[14] = fminf(sqrtf(mdLat2) / 10.0f, 1.0f);
        float cntv = 0.0f;
#pragma unroll
        for (int k = 0; k < 8; k++) {
            o[15 + 2 * k] = sc[k];
            o[16 + 2 * k] = fminf(sqrtf(smin2[k]) / 10.0f, 1.0f);
            cntv += sc[k];            // valid count = sum of sector counts
        }
        o[31] = cnt[3] + cnt[7] + cnt[11];
        float vc = fmaxf(cntv, 1.0f);
        o[32] = fminf(sumd / vc / 10.0f, 1.0f);
    }
}

// ---------------------------------------------------------------------------
// Encoder v3 (reverted known-good): 64 rows/block, 256 threads.
// Thread = 2 cols x 16 rows. W1/W2 via __ldg float2, x/h in shared.
// ---------------------------------------------------------------------------
#define XP 36
#define HP 132

__global__ __launch_bounds__(256, 3) void encoder_kernel(
    const float* __restrict__ W1, const float* __restrict__ b1,
    const float* __restrict__ gamma, const float* __restrict__ beta,
    const float* __restrict__ W2, const float* __restrict__ b2,
    float* __restrict__ out)
{
    __shared__ float sx[64 * XP];
    __shared__ float sh[64 * HP];
    __shared__ float sred[64 * 4];

    const int tid   = threadIdx.x;
    const int cg    = tid & 63;
    const int rg    = tid >> 6;        // 0..3
    const int lane  = tid & 31;
    const int whalf = cg >> 5;
    const int c0    = cg * 2;
    const int r0    = rg * 16;
    const int rowBase = blockIdx.x * 64;

    for (int idx = tid; idx < 64 * FEATN; idx += 256) {
        int r = idx / FEATN, f = idx - r * FEATN;
        sx[r * XP + f] = g_feat[(size_t)rowBase * FEATN + idx];
    }
    for (int idx = tid; idx < 64 * 3; idx += 256) {
        int r = idx / 3;
        sx[r * XP + FEATN + idx % 3] = 0.0f;
    }
    __syncthreads();

    // ---- GEMM1: h = x @ W1 + b1, 16 rows x 2 cols per thread ----
    float accA[16], accB[16];
    {
        const float2 bb = __ldg((const float2*)&b1[c0]);
#pragma unroll
        for (int rr = 0; rr < 16; rr++) { accA[rr] = bb.x; accB[rr] = bb.y; }
#pragma unroll 2
        for (int f4 = 0; f4 < 32; f4 += 4) {
            const float2 w0 = __ldg((const float2*)&W1[(f4 + 0) * EE + c0]);
            const float2 w1 = __ldg((const float2*)&W1[(f4 + 1) * EE + c0]);
            const float2 w2 = __ldg((const float2*)&W1[(f4 + 2) * EE + c0]);
            const float2 w3 = __ldg((const float2*)&W1[(f4 + 3) * EE + c0]);
#pragma unroll
            for (int rr = 0; rr < 16; rr++) {
                const float4 xv = *(const float4*)&sx[(r0 + rr) * XP + f4];
                accA[rr] += xv.x * w0.x + xv.y * w1.x + xv.z * w2.x + xv.w * w3.x;
                accB[rr] += xv.x * w0.y + xv.y * w1.y + xv.z * w2.y + xv.w * w3.y;
            }
        }
        const float2 wl = __ldg((const float2*)&W1[32 * EE + c0]);
#pragma unroll
        for (int rr = 0; rr < 16; rr++) {
            const float xl = sx[(r0 + rr) * XP + 32];
            accA[rr] += xl * wl.x;
            accB[rr] += xl * wl.y;
        }
    }

    // ---- LN partials: each warp covers 64 columns of its rows ----
#pragma unroll
    for (int rr = 0; rr < 16; rr++) {
        float s  = wsum(accA[rr] + accB[rr]);
        float sq = wsum(accA[rr] * accA[rr] + accB[rr] * accB[rr]);
        if (lane == 0) {
            const int r = r0 + rr;
            sred[r * 4 + whalf * 2 + 0] = s;
            sred[r * 4 + whalf * 2 + 1] = sq;
        }
    }
    __syncthreads();

    const float2 gv  = __ldg((const float2*)&gamma[c0]);
    const float2 bev = __ldg((const float2*)&beta[c0]);
#pragma unroll
    for (int rr = 0; rr < 16; rr++) {
        const int r = r0 + rr;
        const float s  = sred[r * 4 + 0] + sred[r * 4 + 2];
        const float sq = sred[r * 4 + 1] + sred[r * 4 + 3];
        const float mu  = s * (1.0f / 128.0f);
        const float var = sq * (1.0f / 128.0f) - mu * mu;
        const float inv = 1.0f / sqrtf(var + 1e-5f);
        float hA = (accA[rr] - mu) * inv * gv.x + bev.x;
        float hB = (accB[rr] - mu) * inv * gv.y + bev.y;
        hA = 0.5f * hA * (1.0f + erff(hA * 0.70710678118654752440f));
        hB = 0.5f * hB * (1.0f + erff(hB * 0.70710678118654752440f));
        *(float2*)&sh[r * HP + c0] = make_float2(hA, hB);
    }
    __syncthreads();

    // ---- GEMM2: out = h @ W2 + b2 ----
    float oA[16], oB[16];
    {
        const float2 bo = __ldg((const float2*)&b2[c0]);
#pragma unroll
        for (int rr = 0; rr < 16; rr++) { oA[rr] = bo.x; oB[rr] = bo.y; }
#pragma unroll 2
        for (int k4 = 0; k4 < EE; k4 += 4) {
            const float2 w0 = __ldg((const float2*)&W2[(k4 + 0) * EE + c0]);
            const float2 w1 = __ldg((const float2*)&W2[(k4 + 1) * EE + c0]);
            const float2 w2 = __ldg((const float2*)&W2[(k4 + 2) * EE + c0]);
            const float2 w3 = __ldg((const float2*)&W2[(k4 + 3) * EE + c0]);
#pragma unroll
            for (int rr = 0; rr < 16; rr++) {
                const float4 hv = *(const float4*)&sh[(r0 + rr) * HP + k4];
                oA[rr] += hv.x * w0.x + hv.y * w1.x + hv.z * w2.x + hv.w * w3.x;
                oB[rr] += hv.x * w0.y + hv.y * w1.y + hv.z * w2.y + hv.w * w3.y;
            }
        }
    }
#pragma unroll
    for (int rr = 0; rr < 16; rr++) {
        float2 o2 = make_float2(oA[rr], oB[rr]);
        *(float2*)&out[(size_t)(rowBase + r0 + rr) * EE + c0] = o2;
    }
}

// ---------------------------------------------------------------------------
extern "C" void kernel_launch(void* const* d_in, const int* in_sizes, int n_in,
                              void* d_out, int out_size) {
    const float* positions = (const float*)d_in[0];
    const void*  mask      = d_in[1];
    const float* W1        = (const float*)d_in[2];
    const float* b1        = (const float*)d_in[3];
    const float* gamma     = (const float*)d_in[4];
    const float* beta      = (const float*)d_in[5];
    const float* W2        = (const float*)d_in[6];
    const float* b2        = (const float*)d_in[7];
    float* out = (float*)d_out;

    feat_kernel<<<dim3(NN / 8, BB), 256>>>(positions, mask);
    encoder_kernel<<<ROWS / 64, 256>>>(W1, b1, gamma, beta, W2, b2, out);
}